// round 6
// baseline (speedup 1.0000x reference)
#include <cuda_runtime.h>
#include <cuda_bf16.h>

// MetaPolicyTransformer: N independent sequences, S=5, D=4, H=2 (hd=2), FF=16, L=3.
// ONE sequence per thread (R1 structure, no spills), f32x2 packed across the
// MODEL dimension: head dim (=2) is exactly one f32x2 pair, so q/k/v/out-proj/FF
// all run on packed math. Broadcast dups go to the ALU pipe (idle in R1).

#define D_ 4
#define S_ 5
#define FF_ 16
#define L_ 3
#define BLK 128

typedef unsigned long long u64;

__device__ __forceinline__ u64 pk2(float lo, float hi) {
    u64 r; asm("mov.b64 %0, {%1, %2};" : "=l"(r) : "f"(lo), "f"(hi)); return r;
}
__device__ __forceinline__ void upk2(u64 v, float& lo, float& hi) {
    asm("mov.b64 {%0, %1}, %2;" : "=f"(lo), "=f"(hi) : "l"(v));
}
__device__ __forceinline__ u64 fma2(u64 a, u64 b, u64 c) {
    u64 r; asm("fma.rn.f32x2 %0, %1, %2, %3;" : "=l"(r) : "l"(a), "l"(b), "l"(c)); return r;
}
__device__ __forceinline__ u64 add2(u64 a, u64 b) {
    u64 r; asm("add.rn.f32x2 %0, %1, %2;" : "=l"(r) : "l"(a), "l"(b)); return r;
}
__device__ __forceinline__ u64 mul2(u64 a, u64 b) {
    u64 r; asm("mul.rn.f32x2 %0, %1, %2;" : "=l"(r) : "l"(a), "l"(b)); return r;
}
__device__ __forceinline__ float ex2a(float x) {
    float r; asm("ex2.approx.f32 %0, %1;" : "=f"(r) : "f"(x)); return r;
}
__device__ __forceinline__ float rcpa(float x) {
    float r; asm("rcp.approx.f32 %0, %1;" : "=f"(r) : "f"(x)); return r;
}
__device__ __forceinline__ u64 relu2(u64 v) {
    float a, b; upk2(v, a, b);
    return pk2(fmaxf(a, 0.0f), fmaxf(b, 0.0f));
}

__global__ __launch_bounds__(BLK) void mpt_kernel(
    const float* __restrict__ xin,   // (N, 4, 4)
    const float* __restrict__ cls,   // (4,)
    const float* __restrict__ Wqkv,  // (3, 12, 4)
    const float* __restrict__ bqkv,  // (3, 12)
    const float* __restrict__ Wo,    // (3, 4, 4)
    const float* __restrict__ bo,    // (3, 4)
    const float* __restrict__ W1,    // (3, 16, 4)
    const float* __restrict__ b1,    // (3, 16)
    const float* __restrict__ W2,    // (3, 4, 16)
    const float* __restrict__ b2,    // (3, 4)
    float* __restrict__ out_fg,      // (N, 4)
    float* __restrict__ out_sub,     // (N, 16)
    int N)
{
    // Weights packed across OUTPUT pairs:
    // sQKV[l][p][c] = {Wqkv[2p][c], Wqkv[2p+1][c]}, q rows (p<2) pre-scaled by 1/sqrt(2)*log2e
    __shared__ u64 sQKV[L_ * 24];
    __shared__ u64 sBQ[L_ * 6];
    __shared__ u64 sWO[L_ * 8];    // [dp][c] = {Wo[2dp][c], Wo[2dp+1][c]}
    __shared__ u64 sBO[L_ * 2];    // {bo[2dp], bo[2dp+1]}
    __shared__ u64 sW1[L_ * 32];   // [fp][c] = {W1[2fp][c], W1[2fp+1][c]}
    __shared__ u64 sB1[L_ * 8];
    __shared__ u64 sW2[L_ * 32];   // [d][fp] = {W2[d][2fp], W2[d][2fp+1]}
    __shared__ float sB2[L_ * 4];
    __shared__ float scls[4];

    const float SCL = 0.70710678118654752f * 1.4426950408889634f; // 1/sqrt2 * log2e

    const int t = threadIdx.x;
    for (int i = t; i < L_ * 24; i += BLK) {
        int l = i / 24, rem = i % 24, p = rem / 4, c = rem % 4;
        float w0 = Wqkv[l * 48 + (2 * p)     * 4 + c];
        float w1 = Wqkv[l * 48 + (2 * p + 1) * 4 + c];
        if (p < 2) { w0 *= SCL; w1 *= SCL; }
        sQKV[i] = pk2(w0, w1);
    }
    for (int i = t; i < L_ * 6; i += BLK) {
        int l = i / 6, p = i % 6;
        float b0 = bqkv[l * 12 + 2 * p];
        float b1v = bqkv[l * 12 + 2 * p + 1];
        if (p < 2) { b0 *= SCL; b1v *= SCL; }
        sBQ[i] = pk2(b0, b1v);
    }
    for (int i = t; i < L_ * 8; i += BLK) {
        int l = i / 8, rem = i % 8, dp = rem / 4, c = rem % 4;
        sWO[i] = pk2(Wo[l * 16 + (2 * dp) * 4 + c], Wo[l * 16 + (2 * dp + 1) * 4 + c]);
    }
    for (int i = t; i < L_ * 2; i += BLK) {
        int l = i / 2, dp = i % 2;
        sBO[i] = pk2(bo[l * 4 + 2 * dp], bo[l * 4 + 2 * dp + 1]);
    }
    for (int i = t; i < L_ * 32; i += BLK) {
        int l = i / 32, rem = i % 32, fp = rem / 4, c = rem % 4;
        sW1[i] = pk2(W1[l * 64 + (2 * fp) * 4 + c], W1[l * 64 + (2 * fp + 1) * 4 + c]);
    }
    for (int i = t; i < L_ * 8; i += BLK) {
        int l = i / 8, fp = i % 8;
        sB1[i] = pk2(b1[l * 16 + 2 * fp], b1[l * 16 + 2 * fp + 1]);
    }
    for (int i = t; i < L_ * 32; i += BLK) {
        int l = i / 32, rem = i % 32, d = rem / 8, fp = rem % 8;
        sW2[i] = pk2(W2[l * 64 + d * 16 + 2 * fp], W2[l * 64 + d * 16 + 2 * fp + 1]);
    }
    for (int i = t; i < L_ * 4; i += BLK) sB2[i] = b2[i];
    if (t < 4) scls[t] = cls[t];
    __syncthreads();

    const int n = blockIdx.x * BLK + t;
    if (n >= N) return;

    // PE: pe[s] = [sin(s), cos(s), sin(.01 s), cos(.01 s)]
    const float pe[S_][D_] = {
        { 0.0f,                  1.0f,                  0.0f,                   1.0f                 },
        { 0.84147098480789651f,  0.54030230586813977f,  0.0099998333341666645f, 0.99995000041666528f },
        { 0.90929742682568170f, -0.41614683654714241f,  0.019998666693333084f,  0.99980000666657776f },
        { 0.14112000805986722f, -0.98999249660044542f,  0.029995500337493652f,  0.99955003374899023f },
        { -0.75680249530792820f,-0.65364362086361194f,  0.039989334186634161f,  0.99920010665856564f }
    };

    float x[S_][D_];
    #pragma unroll
    for (int d = 0; d < D_; d++) x[0][d] = scls[d] + pe[0][d];
    const float4* xp = reinterpret_cast<const float4*>(xin + (size_t)n * 16);
    #pragma unroll
    for (int s = 1; s < S_; s++) {
        float4 r = xp[s - 1];
        x[s][0] = r.x + pe[s][0];
        x[s][1] = r.y + pe[s][1];
        x[s][2] = r.z + pe[s][2];
        x[s][3] = r.w + pe[s][3];
    }

    #pragma unroll 1
    for (int l = 0; l < L_; l++) {
        const u64* wq   = sQKV + l * 24;
        const u64* bqp  = sBQ  + l * 6;
        const u64* wop  = sWO  + l * 8;
        const u64* bop  = sBO  + l * 2;
        const u64* w1p  = sW1  + l * 32;
        const u64* b1p  = sB1  + l * 8;
        const u64* w2p  = sW2  + l * 32;
        const float* b2s = sB2 + l * 4;

        // residual accumulator (packed by output pairs), out-proj bias folded in
        u64 nxp[S_][2];
        #pragma unroll
        for (int s = 0; s < S_; s++) {
            nxp[s][0] = add2(pk2(x[s][0], x[s][1]), bop[0]);
            nxp[s][1] = add2(pk2(x[s][2], x[s][3]), bop[1]);
        }

        // QKV: packed output pairs; pair h of q/k/v is exactly head h's 2 dims
        u64 qp[S_][2], kp[S_][2], vp[S_][2];
        #pragma unroll
        for (int s = 0; s < S_; s++) {
            u64 xd[D_];
            #pragma unroll
            for (int c = 0; c < D_; c++) xd[c] = pk2(x[s][c], x[s][c]);
            #pragma unroll
            for (int p = 0; p < 6; p++) {
                u64 a = bqp[p];
                #pragma unroll
                for (int c = 0; c < D_; c++)
                    a = fma2(xd[c], wq[p * 4 + c], a);
                if (p < 2)      qp[s][p]     = a;
                else if (p < 4) kp[s][p - 2] = a;
                else            vp[s][p - 4] = a;
            }
        }

        // attention per head; out-proj fused into nxp
        #pragma unroll
        for (int h = 0; h < 2; h++) {
            #pragma unroll
            for (int i = 0; i < S_; i++) {
                float e[S_];
                float sum = 0.0f;
                #pragma unroll
                for (int j = 0; j < S_; j++) {
                    u64 m = mul2(qp[i][h], kp[j][h]);   // {q0k0, q1k1}
                    float a, b; upk2(m, a, b);
                    e[j] = ex2a(a + b);                  // exp2 of scaled score
                    sum += e[j];
                }
                float inv = rcpa(sum);
                u64 o = 0ull;
                #pragma unroll
                for (int j = 0; j < S_; j++)
                    o = fma2(pk2(e[j], e[j]), vp[j][h], o);
                float a0, a1; upk2(o, a0, a1);
                a0 *= inv; a1 *= inv;
                u64 d0 = pk2(a0, a0), d1 = pk2(a1, a1);
                #pragma unroll
                for (int dp = 0; dp < 2; dp++) {
                    nxp[i][dp] = fma2(d0, wop[dp * 4 + 2 * h],     nxp[i][dp]);
                    nxp[i][dp] = fma2(d1, wop[dp * 4 + 2 * h + 1], nxp[i][dp]);
                }
            }
        }

        // unpack residual result back to scalar x
        #pragma unroll
        for (int s = 0; s < S_; s++) {
            upk2(nxp[s][0], x[s][0], x[s][1]);
            upk2(nxp[s][1], x[s][2], x[s][3]);
        }

        // FF + residual (packed over FF pairs)
        #pragma unroll
        for (int s = 0; s < S_; s++) {
            u64 xd[D_];
            #pragma unroll
            for (int c = 0; c < D_; c++) xd[c] = pk2(x[s][c], x[s][c]);
            u64 h1p[8];
            #pragma unroll
            for (int fp = 0; fp < 8; fp++) {
                u64 a = b1p[fp];
                #pragma unroll
                for (int c = 0; c < D_; c++)
                    a = fma2(xd[c], w1p[fp * 4 + c], a);
                h1p[fp] = relu2(a);
            }
            #pragma unroll
            for (int d = 0; d < D_; d++) {
                u64 a = 0ull;
                #pragma unroll
                for (int fp = 0; fp < 8; fp++)
                    a = fma2(h1p[fp], w2p[d * 8 + fp], a);
                float pa, pb; upk2(a, pa, pb);
                x[s][d] = x[s][d] + b2s[d] + (pa + pb);
            }
        }
    }

    // outputs
    reinterpret_cast<float4*>(out_fg + (size_t)n * 4)[0] =
        make_float4(x[0][0], x[0][1], x[0][2], x[0][3]);
    float4* sub = reinterpret_cast<float4*>(out_sub + (size_t)n * 16);
    #pragma unroll
    for (int s = 1; s < S_; s++)
        sub[s - 1] = make_float4(x[s][0], x[s][1], x[s][2], x[s][3]);
}

extern "C" void kernel_launch(void* const* d_in, const int* in_sizes, int n_in,
                              void* d_out, int out_size) {
    const float* xin  = (const float*)d_in[0];
    const float* cls  = (const float*)d_in[1];
    const float* Wqkv = (const float*)d_in[2];
    const float* bqkv = (const float*)d_in[3];
    const float* Wo   = (const float*)d_in[4];
    const float* bo   = (const float*)d_in[5];
    const float* W1   = (const float*)d_in[6];
    const float* b1   = (const float*)d_in[7];
    const float* W2   = (const float*)d_in[8];
    const float* b2   = (const float*)d_in[9];

    const int N = in_sizes[0] / 16;
    float* out_fg  = (float*)d_out;
    float* out_sub = (float*)d_out + (size_t)N * 4;

    const int grid = (N + BLK - 1) / BLK;
    mpt_kernel<<<grid, BLK>>>(xin, cls, Wqkv, bqkv, Wo, bo, W1, b1, W2, b2,
                              out_fg, out_sub, N);
}

// round 7
// speedup vs baseline: 1.0195x; 1.0195x over previous
#include <cuda_runtime.h>
#include <cuda_bf16.h>

// MetaPolicyTransformer: N independent sequences, S=5, D=4, H=2 (hd=2), FF=16, L=3.
// One sequence per thread; f32x2 packed across the model dim (head dim == one
// f32x2 pair). R7: BLK=64 for occupancy granularity, packed score j-pairs, and
// W2 packed by output pairs (no horizontal adds in FF epilogue).

#define D_ 4
#define S_ 5
#define FF_ 16
#define L_ 3
#define BLK 64

typedef unsigned long long u64;

__device__ __forceinline__ u64 pk2(float lo, float hi) {
    u64 r; asm("mov.b64 %0, {%1, %2};" : "=l"(r) : "f"(lo), "f"(hi)); return r;
}
__device__ __forceinline__ void upk2(u64 v, float& lo, float& hi) {
    asm("mov.b64 {%0, %1}, %2;" : "=f"(lo), "=f"(hi) : "l"(v));
}
__device__ __forceinline__ u64 fma2(u64 a, u64 b, u64 c) {
    u64 r; asm("fma.rn.f32x2 %0, %1, %2, %3;" : "=l"(r) : "l"(a), "l"(b), "l"(c)); return r;
}
__device__ __forceinline__ u64 add2(u64 a, u64 b) {
    u64 r; asm("add.rn.f32x2 %0, %1, %2;" : "=l"(r) : "l"(a), "l"(b)); return r;
}
__device__ __forceinline__ u64 mul2(u64 a, u64 b) {
    u64 r; asm("mul.rn.f32x2 %0, %1, %2;" : "=l"(r) : "l"(a), "l"(b)); return r;
}
__device__ __forceinline__ float ex2a(float x) {
    float r; asm("ex2.approx.f32 %0, %1;" : "=f"(r) : "f"(x)); return r;
}
__device__ __forceinline__ float rcpa(float x) {
    float r; asm("rcp.approx.f32 %0, %1;" : "=f"(r) : "f"(x)); return r;
}
__device__ __forceinline__ u64 relu2(u64 v) {
    float a, b; upk2(v, a, b);
    return pk2(fmaxf(a, 0.0f), fmaxf(b, 0.0f));
}

__global__ __launch_bounds__(BLK) void mpt_kernel(
    const float* __restrict__ xin,   // (N, 4, 4)
    const float* __restrict__ cls,   // (4,)
    const float* __restrict__ Wqkv,  // (3, 12, 4)
    const float* __restrict__ bqkv,  // (3, 12)
    const float* __restrict__ Wo,    // (3, 4, 4)
    const float* __restrict__ bo,    // (3, 4)
    const float* __restrict__ W1,    // (3, 16, 4)
    const float* __restrict__ b1,    // (3, 16)
    const float* __restrict__ W2,    // (3, 4, 16)
    const float* __restrict__ b2,    // (3, 4)
    float* __restrict__ out_fg,      // (N, 4)
    float* __restrict__ out_sub,     // (N, 16)
    int N)
{
    // sQKV[l][p][c] = {Wqkv[2p][c], Wqkv[2p+1][c]}; q rows (p<2) pre-scaled
    __shared__ u64 sQKV[L_ * 24];
    __shared__ u64 sBQ[L_ * 6];
    __shared__ u64 sWO[L_ * 8];    // [dp][c] = {Wo[2dp][c], Wo[2dp+1][c]}
    __shared__ u64 sBO[L_ * 2];
    __shared__ u64 sW1[L_ * 32];   // [fp][c] = {W1[2fp][c], W1[2fp+1][c]}
    __shared__ u64 sB1[L_ * 8];
    __shared__ u64 sW2[L_ * 32];   // [f][dp] = {W2[2dp][f], W2[2dp+1][f]}
    __shared__ u64 sB2[L_ * 2];    // {b2[2dp], b2[2dp+1]}
    __shared__ float scls[4];

    const float SCL = 0.70710678118654752f * 1.4426950408889634f; // 1/sqrt2 * log2e

    const int t = threadIdx.x;
    for (int i = t; i < L_ * 24; i += BLK) {
        int l = i / 24, rem = i % 24, p = rem / 4, c = rem % 4;
        float w0 = Wqkv[l * 48 + (2 * p)     * 4 + c];
        float w1 = Wqkv[l * 48 + (2 * p + 1) * 4 + c];
        if (p < 2) { w0 *= SCL; w1 *= SCL; }
        sQKV[i] = pk2(w0, w1);
    }
    for (int i = t; i < L_ * 6; i += BLK) {
        int l = i / 6, p = i % 6;
        float b0 = bqkv[l * 12 + 2 * p];
        float b1v = bqkv[l * 12 + 2 * p + 1];
        if (p < 2) { b0 *= SCL; b1v *= SCL; }
        sBQ[i] = pk2(b0, b1v);
    }
    for (int i = t; i < L_ * 8; i += BLK) {
        int l = i / 8, rem = i % 8, dp = rem / 4, c = rem % 4;
        sWO[i] = pk2(Wo[l * 16 + (2 * dp) * 4 + c], Wo[l * 16 + (2 * dp + 1) * 4 + c]);
    }
    for (int i = t; i < L_ * 2; i += BLK) {
        int l = i / 2, dp = i % 2;
        sBO[i] = pk2(bo[l * 4 + 2 * dp], bo[l * 4 + 2 * dp + 1]);
        sB2[i] = pk2(b2[l * 4 + 2 * dp], b2[l * 4 + 2 * dp + 1]);
    }
    for (int i = t; i < L_ * 32; i += BLK) {
        int l = i / 32, rem = i % 32, fp = rem / 4, c = rem % 4;
        sW1[i] = pk2(W1[l * 64 + (2 * fp) * 4 + c], W1[l * 64 + (2 * fp + 1) * 4 + c]);
    }
    for (int i = t; i < L_ * 8; i += BLK) {
        int l = i / 8, fp = i % 8;
        sB1[i] = pk2(b1[l * 16 + 2 * fp], b1[l * 16 + 2 * fp + 1]);
    }
    for (int i = t; i < L_ * 32; i += BLK) {
        int l = i / 32, rem = i % 32, f = rem / 2, dp = rem % 2;
        sW2[i] = pk2(W2[l * 64 + (2 * dp) * 16 + f], W2[l * 64 + (2 * dp + 1) * 16 + f]);
    }
    if (t < 4) scls[t] = cls[t];
    __syncthreads();

    const int n = blockIdx.x * BLK + t;
    if (n >= N) return;

    // PE: pe[s] = [sin(s), cos(s), sin(.01 s), cos(.01 s)]
    const float pe[S_][D_] = {
        { 0.0f,                  1.0f,                  0.0f,                   1.0f                 },
        { 0.84147098480789651f,  0.54030230586813977f,  0.0099998333341666645f, 0.99995000041666528f },
        { 0.90929742682568170f, -0.41614683654714241f,  0.019998666693333084f,  0.99980000666657776f },
        { 0.14112000805986722f, -0.98999249660044542f,  0.029995500337493652f,  0.99955003374899023f },
        { -0.75680249530792820f,-0.65364362086361194f,  0.039989334186634161f,  0.99920010665856564f }
    };

    float x[S_][D_];
    #pragma unroll
    for (int d = 0; d < D_; d++) x[0][d] = scls[d] + pe[0][d];
    const float4* xp = reinterpret_cast<const float4*>(xin + (size_t)n * 16);
    #pragma unroll
    for (int s = 1; s < S_; s++) {
        float4 r = xp[s - 1];
        x[s][0] = r.x + pe[s][0];
        x[s][1] = r.y + pe[s][1];
        x[s][2] = r.z + pe[s][2];
        x[s][3] = r.w + pe[s][3];
    }

    #pragma unroll 1
    for (int l = 0; l < L_; l++) {
        const u64* wq   = sQKV + l * 24;
        const u64* bqp  = sBQ  + l * 6;
        const u64* wop  = sWO  + l * 8;
        const u64* bop  = sBO  + l * 2;
        const u64* w1p  = sW1  + l * 32;
        const u64* b1p  = sB1  + l * 8;
        const u64* w2p  = sW2  + l * 32;
        const u64* b2p  = sB2  + l * 2;

        // residual accumulator (packed pairs), out-proj bias folded in
        u64 nxp[S_][2];
        #pragma unroll
        for (int s = 0; s < S_; s++) {
            nxp[s][0] = add2(pk2(x[s][0], x[s][1]), bop[0]);
            nxp[s][1] = add2(pk2(x[s][2], x[s][3]), bop[1]);
        }

        // QKV packed: pair h of q/k/v == head h's 2 dims
        u64 qp[S_][2], kp[S_][2], vp[S_][2];
        #pragma unroll
        for (int s = 0; s < S_; s++) {
            u64 xd[D_];
            #pragma unroll
            for (int c = 0; c < D_; c++) xd[c] = pk2(x[s][c], x[s][c]);
            #pragma unroll
            for (int p = 0; p < 6; p++) {
                u64 a = bqp[p];
                #pragma unroll
                for (int c = 0; c < D_; c++)
                    a = fma2(xd[c], wq[p * 4 + c], a);
                if (p < 2)      qp[s][p]     = a;
                else if (p < 4) kp[s][p - 2] = a;
                else            vp[s][p - 4] = a;
            }
        }

        // attention per head; scores computed 2-per-instruction via K transpose
        #pragma unroll
        for (int h = 0; h < 2; h++) {
            // transpose K for this head into j-pairs (ALU movs)
            float k0[S_], k1[S_];
            #pragma unroll
            for (int j = 0; j < S_; j++) upk2(kp[j][h], k0[j], k1[j]);
            const u64 kt0a = pk2(k0[0], k0[1]), kt0b = pk2(k0[2], k0[3]);
            const u64 kt1a = pk2(k1[0], k1[1]), kt1b = pk2(k1[2], k1[3]);

            #pragma unroll
            for (int i = 0; i < S_; i++) {
                float q0, q1; upk2(qp[i][h], q0, q1);
                const u64 qb0 = pk2(q0, q0), qb1 = pk2(q1, q1);
                u64 sc01 = fma2(qb1, kt1a, mul2(qb0, kt0a));
                u64 sc23 = fma2(qb1, kt1b, mul2(qb0, kt0b));
                float s0, s1, s2, s3;
                upk2(sc01, s0, s1); upk2(sc23, s2, s3);
                float s4 = fmaf(q1, k1[4], q0 * k0[4]);
                float e0 = ex2a(s0), e1 = ex2a(s1), e2 = ex2a(s2),
                      e3 = ex2a(s3), e4 = ex2a(s4);
                float sum = ((e0 + e1) + (e2 + e3)) + e4;
                float inv = rcpa(sum);
                u64 o = mul2(pk2(e0, e0), vp[0][h]);
                o = fma2(pk2(e1, e1), vp[1][h], o);
                o = fma2(pk2(e2, e2), vp[2][h], o);
                o = fma2(pk2(e3, e3), vp[3][h], o);
                o = fma2(pk2(e4, e4), vp[4][h], o);
                float a0, a1; upk2(o, a0, a1);
                a0 *= inv; a1 *= inv;
                const u64 d0 = pk2(a0, a0), d1 = pk2(a1, a1);
                #pragma unroll
                for (int dp = 0; dp < 2; dp++) {
                    nxp[i][dp] = fma2(d0, wop[dp * 4 + 2 * h],     nxp[i][dp]);
                    nxp[i][dp] = fma2(d1, wop[dp * 4 + 2 * h + 1], nxp[i][dp]);
                }
            }
        }

        // unpack residual result back to scalar x
        #pragma unroll
        for (int s = 0; s < S_; s++) {
            upk2(nxp[s][0], x[s][0], x[s][1]);
            upk2(nxp[s][1], x[s][2], x[s][3]);
        }

        // FF + residual; W2 packed by output pairs (no horizontal adds)
        #pragma unroll
        for (int s = 0; s < S_; s++) {
            u64 xd[D_];
            #pragma unroll
            for (int c = 0; c < D_; c++) xd[c] = pk2(x[s][c], x[s][c]);
            u64 h1p[8];
            #pragma unroll
            for (int fp = 0; fp < 8; fp++) {
                u64 a = b1p[fp];
                #pragma unroll
                for (int c = 0; c < D_; c++)
                    a = fma2(xd[c], w1p[fp * 4 + c], a);
                h1p[fp] = relu2(a);
            }
            u64 acc0 = b2p[0], acc1 = b2p[1];
            #pragma unroll
            for (int fp = 0; fp < 8; fp++) {
                float ha, hb; upk2(h1p[fp], ha, hb);
                const u64 hba = pk2(ha, ha), hbb = pk2(hb, hb);
                acc0 = fma2(hba, w2p[(2 * fp) * 2 + 0], acc0);
                acc1 = fma2(hba, w2p[(2 * fp) * 2 + 1], acc1);
                acc0 = fma2(hbb, w2p[(2 * fp + 1) * 2 + 0], acc0);
                acc1 = fma2(hbb, w2p[(2 * fp + 1) * 2 + 1], acc1);
            }
            u64 y0 = add2(acc0, pk2(x[s][0], x[s][1]));
            u64 y1 = add2(acc1, pk2(x[s][2], x[s][3]));
            upk2(y0, x[s][0], x[s][1]);
            upk2(y1, x[s][2], x[s][3]);
        }
    }

    // outputs
    reinterpret_cast<float4*>(out_fg + (size_t)n * 4)[0] =
        make_float4(x[0][0], x[0][1], x[0][2], x[0][3]);
    float4* sub = reinterpret_cast<float4*>(out_sub + (size_t)n * 16);
    #pragma unroll
    for (int s = 1; s < S_; s++)
        sub[s - 1] = make_float4(x[s][0], x[s][1], x[s][2], x[s][3]);
}

extern "C" void kernel_launch(void* const* d_in, const int* in_sizes, int n_in,
                              void* d_out, int out_size) {
    const float* xin  = (const float*)d_in[0];
    const float* cls  = (const float*)d_in[1];
    const float* Wqkv = (const float*)d_in[2];
    const float* bqkv = (const float*)d_in[3];
    const float* Wo   = (const float*)d_in[4];
    const float* bo   = (const float*)d_in[5];
    const float* W1   = (const float*)d_in[6];
    const float* b1   = (const float*)d_in[7];
    const float* W2   = (const float*)d_in[8];
    const float* b2   = (const float*)d_in[9];

    const int N = in_sizes[0] / 16;
    float* out_fg  = (float*)d_out;
    float* out_sub = (float*)d_out + (size_t)N * 4;

    const int grid = (N + BLK - 1) / BLK;
    mpt_kernel<<<grid, BLK>>>(xin, cls, Wqkv, bqkv, Wo, bo, W1, b1, W2, b2,
                              out_fg, out_sub, N);
}

// round 8
// speedup vs baseline: 1.0268x; 1.0071x over previous
#include <cuda_runtime.h>
#include <cuda_bf16.h>

// MetaPolicyTransformer: N independent sequences, S=5, D=4, H=2 (hd=2), FF=16, L=3.
// One sequence per thread; f32x2 packed across the model dim. R8: all weight
// reads via LDS.128 (ulonglong2) + per-layer/per-head hoisting of reused
// values -> ~2x fewer LDS issue slots (issue-slot count is the binding limit).

#define D_ 4
#define S_ 5
#define FF_ 16
#define L_ 3
#define BLK 64

typedef unsigned long long u64;

__device__ __forceinline__ u64 pk2(float lo, float hi) {
    u64 r; asm("mov.b64 %0, {%1, %2};" : "=l"(r) : "f"(lo), "f"(hi)); return r;
}
__device__ __forceinline__ void upk2(u64 v, float& lo, float& hi) {
    asm("mov.b64 {%0, %1}, %2;" : "=f"(lo), "=f"(hi) : "l"(v));
}
__device__ __forceinline__ u64 fma2(u64 a, u64 b, u64 c) {
    u64 r; asm("fma.rn.f32x2 %0, %1, %2, %3;" : "=l"(r) : "l"(a), "l"(b), "l"(c)); return r;
}
__device__ __forceinline__ u64 add2(u64 a, u64 b) {
    u64 r; asm("add.rn.f32x2 %0, %1, %2;" : "=l"(r) : "l"(a), "l"(b)); return r;
}
__device__ __forceinline__ u64 mul2(u64 a, u64 b) {
    u64 r; asm("mul.rn.f32x2 %0, %1, %2;" : "=l"(r) : "l"(a), "l"(b)); return r;
}
__device__ __forceinline__ float ex2a(float x) {
    float r; asm("ex2.approx.f32 %0, %1;" : "=f"(r) : "f"(x)); return r;
}
__device__ __forceinline__ float rcpa(float x) {
    float r; asm("rcp.approx.f32 %0, %1;" : "=f"(r) : "f"(x)); return r;
}
__device__ __forceinline__ u64 relu2(u64 v) {
    float a, b; upk2(v, a, b);
    return pk2(fmaxf(a, 0.0f), fmaxf(b, 0.0f));
}

__global__ __launch_bounds__(BLK) void mpt_kernel(
    const float* __restrict__ xin,   // (N, 4, 4)
    const float* __restrict__ cls,   // (4,)
    const float* __restrict__ Wqkv,  // (3, 12, 4)
    const float* __restrict__ bqkv,  // (3, 12)
    const float* __restrict__ Wo,    // (3, 4, 4)
    const float* __restrict__ bo,    // (3, 4)
    const float* __restrict__ W1,    // (3, 16, 4)
    const float* __restrict__ b1,    // (3, 16)
    const float* __restrict__ W2,    // (3, 4, 16)
    const float* __restrict__ b2,    // (3, 4)
    float* __restrict__ out_fg,      // (N, 4)
    float* __restrict__ out_sub,     // (N, 16)
    int N)
{
    // Output-pair packed weights, stored as ulonglong2 for LDS.128.
    // sQKV2[l*12 + p*2 + ch] = { {W[2p][2ch],W[2p+1][2ch]}, {W[2p][2ch+1],W[2p+1][2ch+1]} }
    __shared__ ulonglong2 sQKV2[L_ * 12];
    __shared__ ulonglong2 sBQ2[L_ * 3];     // pairs of packed biases
    __shared__ u64        sWO[L_ * 8];      // [dp*4+c] = {Wo[2dp][c], Wo[2dp+1][c]}
    __shared__ u64        sBO[L_ * 2];
    __shared__ ulonglong2 sW12[L_ * 16];    // [fp*2+ch]
    __shared__ ulonglong2 sB12[L_ * 4];
    __shared__ ulonglong2 sW22[L_ * 16];    // [fp*2+fh] = { {W2[0][f],W2[1][f]}, {W2[2][f],W2[3][f]} }, f=2fp+fh
    __shared__ u64        sB2[L_ * 2];
    __shared__ float      scls[4];

    const float SCL = 0.70710678118654752f * 1.4426950408889634f; // 1/sqrt2 * log2e

    const int t = threadIdx.x;
    for (int i = t; i < L_ * 12; i += BLK) {
        int l = i / 12, rem = i % 12, p = rem / 2, ch = rem % 2;
        const float* base = Wqkv + l * 48;
        float a0 = base[(2 * p)     * 4 + 2 * ch];
        float a1 = base[(2 * p + 1) * 4 + 2 * ch];
        float b0 = base[(2 * p)     * 4 + 2 * ch + 1];
        float b1v = base[(2 * p + 1) * 4 + 2 * ch + 1];
        if (p < 2) { a0 *= SCL; a1 *= SCL; b0 *= SCL; b1v *= SCL; }
        sQKV2[i] = make_ulonglong2(pk2(a0, a1), pk2(b0, b1v));
    }
    for (int i = t; i < L_ * 3; i += BLK) {
        int l = i / 3, pp = i % 3;
        const float* base = bqkv + l * 12;
        float s0 = (pp == 0) ? SCL : 1.0f;   // p = 2pp
        float s1 = (2 * pp + 1 < 2) ? SCL : 1.0f;
        u64 lo = pk2(base[4 * pp]     * s0, base[4 * pp + 1] * s0);
        u64 hi = pk2(base[4 * pp + 2] * s1, base[4 * pp + 3] * s1);
        sBQ2[i] = make_ulonglong2(lo, hi);
    }
    for (int i = t; i < L_ * 8; i += BLK) {
        int l = i / 8, rem = i % 8, dp = rem / 4, c = rem % 4;
        sWO[i] = pk2(Wo[l * 16 + (2 * dp) * 4 + c], Wo[l * 16 + (2 * dp + 1) * 4 + c]);
    }
    for (int i = t; i < L_ * 2; i += BLK) {
        int l = i / 2, dp = i % 2;
        sBO[i] = pk2(bo[l * 4 + 2 * dp], bo[l * 4 + 2 * dp + 1]);
        sB2[i] = pk2(b2[l * 4 + 2 * dp], b2[l * 4 + 2 * dp + 1]);
    }
    for (int i = t; i < L_ * 16; i += BLK) {
        int l = i / 16, rem = i % 16, fp = rem / 2, ch = rem % 2;
        const float* base = W1 + l * 64;
        sW12[i] = make_ulonglong2(
            pk2(base[(2 * fp) * 4 + 2 * ch],     base[(2 * fp + 1) * 4 + 2 * ch]),
            pk2(base[(2 * fp) * 4 + 2 * ch + 1], base[(2 * fp + 1) * 4 + 2 * ch + 1]));
    }
    for (int i = t; i < L_ * 4; i += BLK) {
        int l = i / 4, fpp = i % 4;
        const float* base = b1 + l * 16;
        sB12[i] = make_ulonglong2(pk2(base[4 * fpp],     base[4 * fpp + 1]),
                                  pk2(base[4 * fpp + 2], base[4 * fpp + 3]));
    }
    for (int i = t; i < L_ * 16; i += BLK) {
        int l = i / 16, rem = i % 16, fp = rem / 2, fh = rem % 2;
        int f = 2 * fp + fh;
        const float* base = W2 + l * 64;
        sW22[i] = make_ulonglong2(pk2(base[0 * 16 + f], base[1 * 16 + f]),
                                  pk2(base[2 * 16 + f], base[3 * 16 + f]));
    }
    if (t < 4) scls[t] = cls[t];
    __syncthreads();

    const int n = blockIdx.x * BLK + t;
    if (n >= N) return;

    const float pe[S_][D_] = {
        { 0.0f,                  1.0f,                  0.0f,                   1.0f                 },
        { 0.84147098480789651f,  0.54030230586813977f,  0.0099998333341666645f, 0.99995000041666528f },
        { 0.90929742682568170f, -0.41614683654714241f,  0.019998666693333084f,  0.99980000666657776f },
        { 0.14112000805986722f, -0.98999249660044542f,  0.029995500337493652f,  0.99955003374899023f },
        { -0.75680249530792820f,-0.65364362086361194f,  0.039989334186634161f,  0.99920010665856564f }
    };

    float x[S_][D_];
    #pragma unroll
    for (int d = 0; d < D_; d++) x[0][d] = scls[d] + pe[0][d];
    const float4* xp = reinterpret_cast<const float4*>(xin + (size_t)n * 16);
    #pragma unroll
    for (int s = 1; s < S_; s++) {
        float4 r = xp[s - 1];
        x[s][0] = r.x + pe[s][0];
        x[s][1] = r.y + pe[s][1];
        x[s][2] = r.z + pe[s][2];
        x[s][3] = r.w + pe[s][3];
    }

    #pragma unroll 1
    for (int l = 0; l < L_; l++) {
        const ulonglong2* wq2 = sQKV2 + l * 12;
        const ulonglong2* bq2 = sBQ2  + l * 3;
        const u64*        wop = sWO   + l * 8;
        const u64*        bop = sBO   + l * 2;
        const ulonglong2* w1v = sW12  + l * 16;
        const ulonglong2* b1v = sB12  + l * 4;
        const ulonglong2* w2v = sW22  + l * 16;
        const u64*        b2p = sB2   + l * 2;

        // hoist QKV biases once per layer (3 LDS.128)
        u64 bqr[6];
        {
            ulonglong2 bA = bq2[0], bB = bq2[1], bC = bq2[2];
            bqr[0] = bA.x; bqr[1] = bA.y; bqr[2] = bB.x;
            bqr[3] = bB.y; bqr[4] = bC.x; bqr[5] = bC.y;
        }

        // residual accumulator (packed pairs), out-proj bias folded in
        u64 nxp[S_][2];
        #pragma unroll
        for (int s = 0; s < S_; s++) {
            nxp[s][0] = add2(pk2(x[s][0], x[s][1]), bop[0]);
            nxp[s][1] = add2(pk2(x[s][2], x[s][3]), bop[1]);
        }

        // QKV packed: pair h of q/k/v == head h's 2 dims
        u64 qp[S_][2], kp[S_][2], vp[S_][2];
        #pragma unroll
        for (int s = 0; s < S_; s++) {
            u64 xd0 = pk2(x[s][0], x[s][0]);
            u64 xd1 = pk2(x[s][1], x[s][1]);
            u64 xd2 = pk2(x[s][2], x[s][2]);
            u64 xd3 = pk2(x[s][3], x[s][3]);
            #pragma unroll
            for (int p = 0; p < 6; p++) {
                ulonglong2 wA = wq2[p * 2];       // LDS.128
                ulonglong2 wB = wq2[p * 2 + 1];   // LDS.128
                u64 a = bqr[p];
                a = fma2(xd0, wA.x, a);
                a = fma2(xd1, wA.y, a);
                a = fma2(xd2, wB.x, a);
                a = fma2(xd3, wB.y, a);
                if (p < 2)      qp[s][p]     = a;
                else if (p < 4) kp[s][p - 2] = a;
                else            vp[s][p - 4] = a;
            }
        }

        // attention per head
        #pragma unroll
        for (int h = 0; h < 2; h++) {
            // hoist this head's Wo columns (4 LDS.64 total per head)
            const u64 wo00 = wop[0 * 4 + 2 * h], wo01 = wop[0 * 4 + 2 * h + 1];
            const u64 wo10 = wop[1 * 4 + 2 * h], wo11 = wop[1 * 4 + 2 * h + 1];

            float k0[S_], k1[S_];
            #pragma unroll
            for (int j = 0; j < S_; j++) upk2(kp[j][h], k0[j], k1[j]);
            const u64 kt0a = pk2(k0[0], k0[1]), kt0b = pk2(k0[2], k0[3]);
            const u64 kt1a = pk2(k1[0], k1[1]), kt1b = pk2(k1[2], k1[3]);

            #pragma unroll
            for (int i = 0; i < S_; i++) {
                float q0, q1; upk2(qp[i][h], q0, q1);
                const u64 qb0 = pk2(q0, q0), qb1 = pk2(q1, q1);
                u64 sc01 = fma2(qb1, kt1a, mul2(qb0, kt0a));
                u64 sc23 = fma2(qb1, kt1b, mul2(qb0, kt0b));
                float s0, s1, s2, s3;
                upk2(sc01, s0, s1); upk2(sc23, s2, s3);
                float s4 = fmaf(q1, k1[4], q0 * k0[4]);
                float e0 = ex2a(s0), e1 = ex2a(s1), e2 = ex2a(s2),
                      e3 = ex2a(s3), e4 = ex2a(s4);
                float sum = ((e0 + e1) + (e2 + e3)) + e4;
                float inv = rcpa(sum);
                u64 o = mul2(pk2(e0, e0), vp[0][h]);
                o = fma2(pk2(e1, e1), vp[1][h], o);
                o = fma2(pk2(e2, e2), vp[2][h], o);
                o = fma2(pk2(e3, e3), vp[3][h], o);
                o = fma2(pk2(e4, e4), vp[4][h], o);
                float a0, a1; upk2(o, a0, a1);
                a0 *= inv; a1 *= inv;
                const u64 d0 = pk2(a0, a0), d1 = pk2(a1, a1);
                nxp[i][0] = fma2(d0, wo00, nxp[i][0]);
                nxp[i][0] = fma2(d1, wo01, nxp[i][0]);
                nxp[i][1] = fma2(d0, wo10, nxp[i][1]);
                nxp[i][1] = fma2(d1, wo11, nxp[i][1]);
            }
        }

        #pragma unroll
        for (int s = 0; s < S_; s++) {
            upk2(nxp[s][0], x[s][0], x[s][1]);
            upk2(nxp[s][1], x[s][2], x[s][3]);
        }

        // hoist FF b1 (2 LDS.128 -> 4 u64) and b2
        u64 b1r[8];
        {
            ulonglong2 bA = b1v[0], bB = b1v[1], bC = b1v[2], bD = b1v[3];
            b1r[0] = bA.x; b1r[1] = bA.y; b1r[2] = bB.x; b1r[3] = bB.y;
            b1r[4] = bC.x; b1r[5] = bC.y; b1r[6] = bD.x; b1r[7] = bD.y;
        }
        const u64 b2r0 = b2p[0], b2r1 = b2p[1];

        // FF + residual
        #pragma unroll
        for (int s = 0; s < S_; s++) {
            u64 xd0 = pk2(x[s][0], x[s][0]);
            u64 xd1 = pk2(x[s][1], x[s][1]);
            u64 xd2 = pk2(x[s][2], x[s][2]);
            u64 xd3 = pk2(x[s][3], x[s][3]);
            u64 acc0 = b2r0, acc1 = b2r1;
            #pragma unroll
            for (int fp = 0; fp < 8; fp++) {
                ulonglong2 wA = w1v[fp * 2];       // LDS.128
                ulonglong2 wB = w1v[fp * 2 + 1];   // LDS.128
                u64 a = b1r[fp];
                a = fma2(xd0, wA.x, a);
                a = fma2(xd1, wA.y, a);
                a = fma2(xd2, wB.x, a);
                a = fma2(xd3, wB.y, a);
                u64 h1 = relu2(a);
                float ha, hb; upk2(h1, ha, hb);
                const u64 hba = pk2(ha, ha), hbb = pk2(hb, hb);
                ulonglong2 w2a = w2v[fp * 2];       // LDS.128: f=2fp  -> {dp0, dp1}
                ulonglong2 w2b = w2v[fp * 2 + 1];   // LDS.128: f=2fp+1
                acc0 = fma2(hba, w2a.x, acc0);
                acc1 = fma2(hba, w2a.y, acc1);
                acc0 = fma2(hbb, w2b.x, acc0);
                acc1 = fma2(hbb, w2b.y, acc1);
            }
            u64 y0 = add2(acc0, pk2(x[s][0], x[s][1]));
            u64 y1 = add2(acc1, pk2(x[s][2], x[s][3]));
            upk2(y0, x[s][0], x[s][1]);
            upk2(y1, x[s][2], x[s][3]);
        }
    }

    // outputs
    reinterpret_cast<float4*>(out_fg + (size_t)n * 4)[0] =
        make_float4(x[0][0], x[0][1], x[0][2], x[0][3]);
    float4* sub = reinterpret_cast<float4*>(out_sub + (size_t)n * 16);
    #pragma unroll
    for (int s = 1; s < S_; s++)
        sub[s - 1] = make_float4(x[s][0], x[s][1], x[s][2], x[s][3]);
}

extern "C" void kernel_launch(void* const* d_in, const int* in_sizes, int n_in,
                              void* d_out, int out_size) {
    const float* xin  = (const float*)d_in[0];
    const float* cls  = (const float*)d_in[1];
    const float* Wqkv = (const float*)d_in[2];
    const float* bqkv = (const float*)d_in[3];
    const float* Wo   = (const float*)d_in[4];
    const float* bo   = (const float*)d_in[5];
    const float* W1   = (const float*)d_in[6];
    const float* b1   = (const float*)d_in[7];
    const float* W2   = (const float*)d_in[8];
    const float* b2   = (const float*)d_in[9];

    const int N = in_sizes[0] / 16;
    float* out_fg  = (float*)d_out;
    float* out_sub = (float*)d_out + (size_t)N * 4;

    const int grid = (N + BLK - 1) / BLK;
    mpt_kernel<<<grid, BLK>>>(xin, cls, Wqkv, bqkv, Wo, bo, W1, b1, W2, b2,
                              out_fg, out_sub, N);
}

// round 9
// speedup vs baseline: 1.0375x; 1.0105x over previous
#include <cuda_runtime.h>
#include <cuda_bf16.h>

// MetaPolicyTransformer: N independent sequences, S=5, D=4, H=2 (hd=2), FF=16, L=3.
// One sequence per thread; f32x2 packed across the model dim. R9: per-head
// QKV computation (same fma2 count, reordered) to shrink the attention live
// register set ~30 regs -> higher occupancy -> better fma-pipe latency hiding.

#define D_ 4
#define S_ 5
#define FF_ 16
#define L_ 3
#define BLK 64

typedef unsigned long long u64;

__device__ __forceinline__ u64 pk2(float lo, float hi) {
    u64 r; asm("mov.b64 %0, {%1, %2};" : "=l"(r) : "f"(lo), "f"(hi)); return r;
}
__device__ __forceinline__ void upk2(u64 v, float& lo, float& hi) {
    asm("mov.b64 {%0, %1}, %2;" : "=f"(lo), "=f"(hi) : "l"(v));
}
__device__ __forceinline__ u64 fma2(u64 a, u64 b, u64 c) {
    u64 r; asm("fma.rn.f32x2 %0, %1, %2, %3;" : "=l"(r) : "l"(a), "l"(b), "l"(c)); return r;
}
__device__ __forceinline__ u64 add2(u64 a, u64 b) {
    u64 r; asm("add.rn.f32x2 %0, %1, %2;" : "=l"(r) : "l"(a), "l"(b)); return r;
}
__device__ __forceinline__ u64 mul2(u64 a, u64 b) {
    u64 r; asm("mul.rn.f32x2 %0, %1, %2;" : "=l"(r) : "l"(a), "l"(b)); return r;
}
__device__ __forceinline__ float ex2a(float x) {
    float r; asm("ex2.approx.f32 %0, %1;" : "=f"(r) : "f"(x)); return r;
}
__device__ __forceinline__ float rcpa(float x) {
    float r; asm("rcp.approx.f32 %0, %1;" : "=f"(r) : "f"(x)); return r;
}
__device__ __forceinline__ u64 relu2(u64 v) {
    float a, b; upk2(v, a, b);
    return pk2(fmaxf(a, 0.0f), fmaxf(b, 0.0f));
}

__global__ __launch_bounds__(BLK) void mpt_kernel(
    const float* __restrict__ xin,   // (N, 4, 4)
    const float* __restrict__ cls,   // (4,)
    const float* __restrict__ Wqkv,  // (3, 12, 4)
    const float* __restrict__ bqkv,  // (3, 12)
    const float* __restrict__ Wo,    // (3, 4, 4)
    const float* __restrict__ bo,    // (3, 4)
    const float* __restrict__ W1,    // (3, 16, 4)
    const float* __restrict__ b1,    // (3, 16)
    const float* __restrict__ W2,    // (3, 4, 16)
    const float* __restrict__ b2,    // (3, 4)
    float* __restrict__ out_fg,      // (N, 4)
    float* __restrict__ out_sub,     // (N, 16)
    int N)
{
    // Output-pair packed weights as ulonglong2 (LDS.128).
    __shared__ ulonglong2 sQKV2[L_ * 12];
    __shared__ ulonglong2 sBQ2[L_ * 3];
    __shared__ u64        sWO[L_ * 8];      // [dp*4+c] = {Wo[2dp][c], Wo[2dp+1][c]}
    __shared__ u64        sBO[L_ * 2];
    __shared__ ulonglong2 sW12[L_ * 16];
    __shared__ ulonglong2 sB12[L_ * 4];
    __shared__ ulonglong2 sW22[L_ * 16];    // [fp*2+fh] = { {W2[0][f],W2[1][f]}, {W2[2][f],W2[3][f]} }
    __shared__ u64        sB2[L_ * 2];
    __shared__ float      scls[4];

    const float SCL = 0.70710678118654752f * 1.4426950408889634f; // 1/sqrt2 * log2e

    const int t = threadIdx.x;
    for (int i = t; i < L_ * 12; i += BLK) {
        int l = i / 12, rem = i % 12, p = rem / 2, ch = rem % 2;
        const float* base = Wqkv + l * 48;
        float a0 = base[(2 * p)     * 4 + 2 * ch];
        float a1 = base[(2 * p + 1) * 4 + 2 * ch];
        float b0 = base[(2 * p)     * 4 + 2 * ch + 1];
        float b1v = base[(2 * p + 1) * 4 + 2 * ch + 1];
        if (p < 2) { a0 *= SCL; a1 *= SCL; b0 *= SCL; b1v *= SCL; }
        sQKV2[i] = make_ulonglong2(pk2(a0, a1), pk2(b0, b1v));
    }
    for (int i = t; i < L_ * 3; i += BLK) {
        int l = i / 3, pp = i % 3;
        const float* base = bqkv + l * 12;
        float s0 = (pp == 0) ? SCL : 1.0f;
        u64 lo = pk2(base[4 * pp]     * s0, base[4 * pp + 1] * s0);
        u64 hi = pk2(base[4 * pp + 2], base[4 * pp + 3]);
        sBQ2[i] = make_ulonglong2(lo, hi);
    }
    for (int i = t; i < L_ * 8; i += BLK) {
        int l = i / 8, rem = i % 8, dp = rem / 4, c = rem % 4;
        sWO[i] = pk2(Wo[l * 16 + (2 * dp) * 4 + c], Wo[l * 16 + (2 * dp + 1) * 4 + c]);
    }
    for (int i = t; i < L_ * 2; i += BLK) {
        int l = i / 2, dp = i % 2;
        sBO[i] = pk2(bo[l * 4 + 2 * dp], bo[l * 4 + 2 * dp + 1]);
        sB2[i] = pk2(b2[l * 4 + 2 * dp], b2[l * 4 + 2 * dp + 1]);
    }
    for (int i = t; i < L_ * 16; i += BLK) {
        int l = i / 16, rem = i % 16, fp = rem / 2, ch = rem % 2;
        const float* base = W1 + l * 64;
        sW12[i] = make_ulonglong2(
            pk2(base[(2 * fp) * 4 + 2 * ch],     base[(2 * fp + 1) * 4 + 2 * ch]),
            pk2(base[(2 * fp) * 4 + 2 * ch + 1], base[(2 * fp + 1) * 4 + 2 * ch + 1]));
    }
    for (int i = t; i < L_ * 4; i += BLK) {
        int l = i / 4, fpp = i % 4;
        const float* base = b1 + l * 16;
        sB12[i] = make_ulonglong2(pk2(base[4 * fpp],     base[4 * fpp + 1]),
                                  pk2(base[4 * fpp + 2], base[4 * fpp + 3]));
    }
    for (int i = t; i < L_ * 16; i += BLK) {
        int l = i / 16, rem = i % 16, fp = rem / 2, fh = rem % 2;
        int f = 2 * fp + fh;
        const float* base = W2 + l * 64;
        sW22[i] = make_ulonglong2(pk2(base[0 * 16 + f], base[1 * 16 + f]),
                                  pk2(base[2 * 16 + f], base[3 * 16 + f]));
    }
    if (t < 4) scls[t] = cls[t];
    __syncthreads();

    const int n = blockIdx.x * BLK + t;
    if (n >= N) return;

    const float pe[S_][D_] = {
        { 0.0f,                  1.0f,                  0.0f,                   1.0f                 },
        { 0.84147098480789651f,  0.54030230586813977f,  0.0099998333341666645f, 0.99995000041666528f },
        { 0.90929742682568170f, -0.41614683654714241f,  0.019998666693333084f,  0.99980000666657776f },
        { 0.14112000805986722f, -0.98999249660044542f,  0.029995500337493652f,  0.99955003374899023f },
        { -0.75680249530792820f,-0.65364362086361194f,  0.039989334186634161f,  0.99920010665856564f }
    };

    float x[S_][D_];
    #pragma unroll
    for (int d = 0; d < D_; d++) x[0][d] = scls[d] + pe[0][d];
    const float4* xp = reinterpret_cast<const float4*>(xin + (size_t)n * 16);
    #pragma unroll
    for (int s = 1; s < S_; s++) {
        float4 r = xp[s - 1];
        x[s][0] = r.x + pe[s][0];
        x[s][1] = r.y + pe[s][1];
        x[s][2] = r.z + pe[s][2];
        x[s][3] = r.w + pe[s][3];
    }

    #pragma unroll 1
    for (int l = 0; l < L_; l++) {
        const ulonglong2* wq2 = sQKV2 + l * 12;
        const ulonglong2* bq2 = sBQ2  + l * 3;
        const u64*        wop = sWO   + l * 8;
        const u64*        bop = sBO   + l * 2;
        const ulonglong2* w1v = sW12  + l * 16;
        const ulonglong2* b1v = sB12  + l * 4;
        const ulonglong2* w2v = sW22  + l * 16;
        const u64*        b2p = sB2   + l * 2;

        // residual accumulator (packed pairs), out-proj bias folded in
        u64 nxp[S_][2];
        #pragma unroll
        for (int s = 0; s < S_; s++) {
            nxp[s][0] = add2(pk2(x[s][0], x[s][1]), bop[0]);
            nxp[s][1] = add2(pk2(x[s][2], x[s][3]), bop[1]);
        }

        // attention, one head at a time; q/k/v computed per head (same total
        // fma2 count as computing all pairs upfront, but half the live state)
        #pragma unroll 1
        for (int h = 0; h < 2; h++) {
            // hoist per-head biases and Wo columns
            ulonglong2 bqA = bq2[h >> 1], bqB = bq2[1], bqC = bq2[2];
            const u64 bq_q = (h == 0) ? bq2[0].x : bq2[0].y;
            const u64 bq_k = (h == 0) ? bqB.x : bqB.y;
            const u64 bq_v = (h == 0) ? bqC.x : bqC.y;
            (void)bqA;
            const u64 wo00 = wop[0 * 4 + 2 * h], wo01 = wop[0 * 4 + 2 * h + 1];
            const u64 wo10 = wop[1 * 4 + 2 * h], wo11 = wop[1 * 4 + 2 * h + 1];

            u64 qh[S_], vh[S_];
            float k0[S_], k1[S_];
            #pragma unroll
            for (int s = 0; s < S_; s++) {
                u64 xd0 = pk2(x[s][0], x[s][0]);
                u64 xd1 = pk2(x[s][1], x[s][1]);
                u64 xd2 = pk2(x[s][2], x[s][2]);
                u64 xd3 = pk2(x[s][3], x[s][3]);
                // q pair: p = h
                {
                    ulonglong2 wA = wq2[h * 2], wB = wq2[h * 2 + 1];
                    u64 a = bq_q;
                    a = fma2(xd0, wA.x, a);
                    a = fma2(xd1, wA.y, a);
                    a = fma2(xd2, wB.x, a);
                    a = fma2(xd3, wB.y, a);
                    qh[s] = a;
                }
                // k pair: p = 2 + h (immediately transposed to scalars)
                {
                    ulonglong2 wA = wq2[(2 + h) * 2], wB = wq2[(2 + h) * 2 + 1];
                    u64 a = bq_k;
                    a = fma2(xd0, wA.x, a);
                    a = fma2(xd1, wA.y, a);
                    a = fma2(xd2, wB.x, a);
                    a = fma2(xd3, wB.y, a);
                    upk2(a, k0[s], k1[s]);
                }
                // v pair: p = 4 + h
                {
                    ulonglong2 wA = wq2[(4 + h) * 2], wB = wq2[(4 + h) * 2 + 1];
                    u64 a = bq_v;
                    a = fma2(xd0, wA.x, a);
                    a = fma2(xd1, wA.y, a);
                    a = fma2(xd2, wB.x, a);
                    a = fma2(xd3, wB.y, a);
                    vh[s] = a;
                }
            }

            const u64 kt0a = pk2(k0[0], k0[1]), kt0b = pk2(k0[2], k0[3]);
            const u64 kt1a = pk2(k1[0], k1[1]), kt1b = pk2(k1[2], k1[3]);

            #pragma unroll
            for (int i = 0; i < S_; i++) {
                float q0, q1; upk2(qh[i], q0, q1);
                const u64 qb0 = pk2(q0, q0), qb1 = pk2(q1, q1);
                u64 sc01 = fma2(qb1, kt1a, mul2(qb0, kt0a));
                u64 sc23 = fma2(qb1, kt1b, mul2(qb0, kt0b));
                float s0, s1, s2, s3;
                upk2(sc01, s0, s1); upk2(sc23, s2, s3);
                float s4 = fmaf(q1, k1[4], q0 * k0[4]);
                float e0 = ex2a(s0), e1 = ex2a(s1), e2 = ex2a(s2),
                      e3 = ex2a(s3), e4 = ex2a(s4);
                // packed partial sum
                u64 psum = add2(pk2(e0, e1), pk2(e2, e3));
                float pa, pb; upk2(psum, pa, pb);
                float inv = rcpa((pa + pb) + e4);
                u64 o = mul2(pk2(e0, e0), vh[0]);
                o = fma2(pk2(e1, e1), vh[1], o);
                o = fma2(pk2(e2, e2), vh[2], o);
                o = fma2(pk2(e3, e3), vh[3], o);
                o = fma2(pk2(e4, e4), vh[4], o);
                o = mul2(o, pk2(inv, inv));
                float a0, a1; upk2(o, a0, a1);
                const u64 d0 = pk2(a0, a0), d1 = pk2(a1, a1);
                nxp[i][0] = fma2(d0, wo00, nxp[i][0]);
                nxp[i][0] = fma2(d1, wo01, nxp[i][0]);
                nxp[i][1] = fma2(d0, wo10, nxp[i][1]);
                nxp[i][1] = fma2(d1, wo11, nxp[i][1]);
            }
        }

        #pragma unroll
        for (int s = 0; s < S_; s++) {
            upk2(nxp[s][0], x[s][0], x[s][1]);
            upk2(nxp[s][1], x[s][2], x[s][3]);
        }

        // hoist FF biases
        u64 b1r[8];
        {
            ulonglong2 bA = b1v[0], bB = b1v[1], bC = b1v[2], bD = b1v[3];
            b1r[0] = bA.x; b1r[1] = bA.y; b1r[2] = bB.x; b1r[3] = bB.y;
            b1r[4] = bC.x; b1r[5] = bC.y; b1r[6] = bD.x; b1r[7] = bD.y;
        }
        const u64 b2r0 = b2p[0], b2r1 = b2p[1];

        // FF + residual
        #pragma unroll
        for (int s = 0; s < S_; s++) {
            u64 xd0 = pk2(x[s][0], x[s][0]);
            u64 xd1 = pk2(x[s][1], x[s][1]);
            u64 xd2 = pk2(x[s][2], x[s][2]);
            u64 xd3 = pk2(x[s][3], x[s][3]);
            u64 acc0 = b2r0, acc1 = b2r1;
            #pragma unroll
            for (int fp = 0; fp < 8; fp++) {
                ulonglong2 wA = w1v[fp * 2];
                ulonglong2 wB = w1v[fp * 2 + 1];
                u64 a = b1r[fp];
                a = fma2(xd0, wA.x, a);
                a = fma2(xd1, wA.y, a);
                a = fma2(xd2, wB.x, a);
                a = fma2(xd3, wB.y, a);
                u64 h1 = relu2(a);
                float ha, hb; upk2(h1, ha, hb);
                const u64 hba = pk2(ha, ha), hbb = pk2(hb, hb);
                ulonglong2 w2a = w2v[fp * 2];
                ulonglong2 w2b = w2v[fp * 2 + 1];
                acc0 = fma2(hba, w2a.x, acc0);
                acc1 = fma2(hba, w2a.y, acc1);
                acc0 = fma2(hbb, w2b.x, acc0);
                acc1 = fma2(hbb, w2b.y, acc1);
            }
            u64 y0 = add2(acc0, pk2(x[s][0], x[s][1]));
            u64 y1 = add2(acc1, pk2(x[s][2], x[s][3]));
            upk2(y0, x[s][0], x[s][1]);
            upk2(y1, x[s][2], x[s][3]);
        }
    }

    // outputs
    reinterpret_cast<float4*>(out_fg + (size_t)n * 4)[0] =
        make_float4(x[0][0], x[0][1], x[0][2], x[0][3]);
    float4* sub = reinterpret_cast<float4*>(out_sub + (size_t)n * 16);
    #pragma unroll
    for (int s = 1; s < S_; s++)
        sub[s - 1] = make_float4(x[s][0], x[s][1], x[s][2], x[s][3]);
}

extern "C" void kernel_launch(void* const* d_in, const int* in_sizes, int n_in,
                              void* d_out, int out_size) {
    const float* xin  = (const float*)d_in[0];
    const float* cls  = (const float*)d_in[1];
    const float* Wqkv = (const float*)d_in[2];
    const float* bqkv = (const float*)d_in[3];
    const float* Wo   = (const float*)d_in[4];
    const float* bo   = (const float*)d_in[5];
    const float* W1   = (const float*)d_in[6];
    const float* b1   = (const float*)d_in[7];
    const float* W2   = (const float*)d_in[8];
    const float* b2   = (const float*)d_in[9];

    const int N = in_sizes[0] / 16;
    float* out_fg  = (float*)d_out;
    float* out_sub = (float*)d_out + (size_t)N * 4;

    const int grid = (N + BLK - 1) / BLK;
    mpt_kernel<<<grid, BLK>>>(xin, cls, Wqkv, bqkv, Wo, bo, W1, b1, W2, b2,
                              out_fg, out_sub, N);
}